// round 11
// baseline (speedup 1.0000x reference)
#include <cuda_runtime.h>
#include <cuda_fp16.h>

// ScaledDotProductAttention: B=4, H=1, S=4096, D=16, fp32.
// out = [context (B*S*D) | attn (B*S*S)]
// scores = QK^T/4 + (w*link + b); masked(true) -> -1e9; softmax; context = attn @ V.
// No-max softmax; predicated MUFU.EX2; fp16 e buffer; FFMA2 packed math.
// TQ=8 kept (K/V L1 amortization). Phase E lane-splits the d-dimension
// (4 dims/lane) so accumulators shrink 128->32 regs; reg ceiling ~140 ->
// 3 CTAs/SM = 12 warps at UNCHANGED grid/traffic.

#define BATCH 4
#define SEQ   4096
#define DIM   16
#define TQ    8            // q-rows per CTA
#define NT    128          // threads per CTA
#define NWARP (NT / 32)

#define SMEM_BYTES (TQ * SEQ * 2)   // 65536 B fp16 e buffer

typedef unsigned long long u64;

__device__ __forceinline__ u64 pk2(float lo, float hi) {
    u64 r; asm("mov.b64 %0, {%1, %2};" : "=l"(r) : "f"(lo), "f"(hi)); return r;
}
__device__ __forceinline__ void upk2(u64 v, float& lo, float& hi) {
    asm("mov.b64 {%0, %1}, %2;" : "=f"(lo), "=f"(hi) : "l"(v));
}
__device__ __forceinline__ u64 fma2(u64 a, u64 b, u64 c) {
    u64 d; asm("fma.rn.f32x2 %0, %1, %2, %3;" : "=l"(d) : "l"(a), "l"(b), "l"(c)); return d;
}
__device__ __forceinline__ u64 mul2(u64 a, u64 b) {
    u64 d; asm("mul.rn.f32x2 %0, %1, %2;" : "=l"(d) : "l"(a), "l"(b)); return d;
}

__global__ __launch_bounds__(NT, 3)
void sdpa_fused_kernel(const float* __restrict__ Qp,
                       const float* __restrict__ Kp,
                       const float* __restrict__ Vp,
                       const int*   __restrict__ Mp,
                       const float* __restrict__ Lp,
                       const float* __restrict__ swp,
                       const float* __restrict__ sbp,
                       float* __restrict__ ctx,
                       float* __restrict__ attn)
{
    extern __shared__ __half scr[];                // TQ*SEQ fp16 e values
    __shared__ float qs[TQ * DIM];
    __shared__ float redw[TQ * NWARP];
    __shared__ float sinv[TQ];
    __shared__ float redc[NWARP * 128];            // context partials (2 KB)

    const int tid = threadIdx.x;
    const int wp  = tid >> 5;
    const int ln  = tid & 31;
    const int b   = blockIdx.x / (SEQ / TQ);
    const int q0  = (blockIdx.x % (SEQ / TQ)) * TQ;

    const float LOG2E = 1.44269504088896f;
    const float w2 = (*swp) * LOG2E;
    const float b2 = (*sbp) * LOG2E;
    const float S2 = 0.25f * LOG2E;                // (1/sqrt(16)) * log2e

    qs[tid] = Qp[((size_t)b * SEQ + q0) * DIM + tid];   // NT == TQ*DIM == 128
    __syncthreads();

    u64 q2[TQ * 8];
    #pragma unroll
    for (int q = 0; q < TQ; q++)
        #pragma unroll
        for (int i = 0; i < 8; i++)
            q2[q * 8 + i] = pk2(qs[q * DIM + 2 * i], qs[q * DIM + 2 * i + 1]);

    const float4* K4 = (const float4*)(Kp + (size_t)b * SEQ * DIM);
    const float4* V4 = (const float4*)(Vp + (size_t)b * SEQ * DIM);
    const float*  Lb = Lp + (size_t)b * SEQ * SEQ;
    const int*    Mb = Mp + (size_t)b * SEQ * SEQ;
    float* Ab = attn + (size_t)b * SEQ * SEQ;

    // ============ Phase A: e = ex2(score*log2e) -> fp16 smem; row sums ============
    float sloc[TQ];
    #pragma unroll
    for (int q = 0; q < TQ; q++) sloc[q] = 0.0f;

    #pragma unroll 2
    for (int k = tid; k < SEQ; k += NT) {
        float4 k0 = K4[4 * k + 0];
        float4 k1 = K4[4 * k + 1];
        float4 k2 = K4[4 * k + 2];
        float4 k3 = K4[4 * k + 3];
        u64 kk[8];
        kk[0] = pk2(k0.x, k0.y); kk[1] = pk2(k0.z, k0.w);
        kk[2] = pk2(k1.x, k1.y); kk[3] = pk2(k1.z, k1.w);
        kk[4] = pk2(k2.x, k2.y); kk[5] = pk2(k2.z, k2.w);
        kk[6] = pk2(k3.x, k3.y); kk[7] = pk2(k3.z, k3.w);

        float lk[TQ];
        int   mk[TQ];
        #pragma unroll
        for (int q = 0; q < TQ; q++) lk[q] = Lb[(size_t)(q0 + q) * SEQ + k];
        #pragma unroll
        for (int q = 0; q < TQ; q++) mk[q] = Mb[(size_t)(q0 + q) * SEQ + k];

        #pragma unroll
        for (int q = 0; q < TQ; q++) {
            const u64* qq = &q2[q * 8];
            u64 d2 = mul2(qq[0], kk[0]);
            d2 = fma2(qq[1], kk[1], d2);
            d2 = fma2(qq[2], kk[2], d2);
            d2 = fma2(qq[3], kk[3], d2);
            d2 = fma2(qq[4], kk[4], d2);
            d2 = fma2(qq[5], kk[5], d2);
            d2 = fma2(qq[6], kk[6], d2);
            d2 = fma2(qq[7], kk[7], d2);
            float dl, dh;
            upk2(d2, dl, dh);
            float dot = dl + dh;
            float sc2 = fmaf(w2, lk[q], b2);
            sc2 = fmaf(dot, S2, sc2);
            float e = 0.0f;
            if (!mk[q])
                asm("ex2.approx.ftz.f32 %0, %1;" : "=f"(e) : "f"(sc2));
            __half he = __float2half_rn(e);
            scr[q * SEQ + k] = he;
            sloc[q] += __half2float(he);       // sum the ROUNDED value
        }
    }

    // ---- reduce row sums ----
    #pragma unroll
    for (int q = 0; q < TQ; q++) {
        #pragma unroll
        for (int o = 16; o > 0; o >>= 1)
            sloc[q] += __shfl_xor_sync(0xffffffffu, sloc[q], o);
    }
    if (ln == 0) {
        #pragma unroll
        for (int q = 0; q < TQ; q++) redw[q * NWARP + wp] = sloc[q];
    }
    __syncthreads();
    if (tid < TQ) {
        float s = 0.0f;
        #pragma unroll
        for (int t = 0; t < NWARP; t++) s += redw[tid * NWARP + t];
        sinv[tid] = 1.0f / s;
    }
    __syncthreads();

    float inv[TQ];
    #pragma unroll
    for (int q = 0; q < TQ; q++) inv[q] = sinv[q];

    // ============ Phase E1: unnormalized ctx accumulate, d-split lanes ============
    // lane = (g, c): g = ln>>2 picks k-row within the warp's 8-row group,
    // c = ln&3 owns dims 4c..4c+3. V loads: 32 lanes = 512B contiguous.
    const int c = ln & 3;
    const int g = ln >> 2;

    u64 acc2[TQ * 2];                       // [q][2]: dims (4c,4c+1),(4c+2,4c+3)
    #pragma unroll
    for (int i = 0; i < TQ * 2; i++) acc2[i] = 0ull;

    #pragma unroll 2
    for (int k0 = wp * 8; k0 < SEQ; k0 += 32) {
        const int kr = k0 + g;
        float4 v = V4[kr * 4 + c];
        u64 vlo = pk2(v.x, v.y);
        u64 vhi = pk2(v.z, v.w);
        #pragma unroll
        for (int q = 0; q < TQ; q++) {
            float e = __half2float(scr[q * SEQ + kr]);   // broadcast over c
            u64 ee = pk2(e, e);
            acc2[q * 2]     = fma2(ee, vlo, acc2[q * 2]);
            acc2[q * 2 + 1] = fma2(ee, vhi, acc2[q * 2 + 1]);
        }
    }

    // reduce over g (xor 4,8,16), then lanes g==0 write scaled partials
    float accf[TQ * 4];
    #pragma unroll
    for (int i = 0; i < TQ * 2; i++)
        upk2(acc2[i], accf[2 * i], accf[2 * i + 1]);
    #pragma unroll
    for (int o = 4; o <= 16; o <<= 1) {
        #pragma unroll
        for (int i = 0; i < TQ * 4; i++)
            accf[i] += __shfl_xor_sync(0xffffffffu, accf[i], o);
    }
    if (g == 0) {
        #pragma unroll
        for (int q = 0; q < TQ; q++)
            *(float4*)&redc[wp * 128 + q * 16 + c * 4] =
                make_float4(accf[q * 4] * inv[q],     accf[q * 4 + 1] * inv[q],
                            accf[q * 4 + 2] * inv[q], accf[q * 4 + 3] * inv[q]);
    }

    // ============ Phase E2: attn = e * inv (coalesced stream) ============
    const __half2* scr2 = (const __half2*)scr;
    #pragma unroll 2
    for (int k = tid; k < SEQ / 2; k += NT) {
        #pragma unroll
        for (int q = 0; q < TQ; q++) {
            __half2 h2 = scr2[q * (SEQ / 2) + k];
            float2 ef = __half22float2(h2);
            float2 a = make_float2(ef.x * inv[q], ef.y * inv[q]);
            *(float2*)&Ab[(size_t)(q0 + q) * SEQ + 2 * k] = a;
        }
    }

    __syncthreads();
    {   // NT == 128: each thread finalizes one (q, d)
        float s = 0.0f;
        #pragma unroll
        for (int ww = 0; ww < NWARP; ww++)
            s += redc[ww * 128 + tid];
        const int q = tid >> 4, d = tid & 15;
        ctx[((size_t)b * SEQ + q0 + q) * DIM + d] = s;
    }
}

extern "C" void kernel_launch(void* const* d_in, const int* in_sizes, int n_in,
                              void* d_out, int out_size)
{
    const float* Q  = (const float*)d_in[0];
    const float* K  = (const float*)d_in[1];
    const float* V  = (const float*)d_in[2];
    const int*   M  = (const int*)d_in[3];
    const float* L  = (const float*)d_in[4];
    const float* sw = (const float*)d_in[5];
    const float* sb = (const float*)d_in[6];

    float* ctx  = (float*)d_out;                               // B*S*D
    float* attn = (float*)d_out + (size_t)BATCH * SEQ * DIM;   // B*S*S

    cudaFuncSetAttribute(sdpa_fused_kernel,
                         cudaFuncAttributeMaxDynamicSharedMemorySize, SMEM_BYTES);

    dim3 grid(BATCH * (SEQ / TQ));
    sdpa_fused_kernel<<<grid, NT, SMEM_BYTES>>>(Q, K, V, M, L, sw, sb, ctx, attn);
}

// round 12
// speedup vs baseline: 1.8911x; 1.8911x over previous
#include <cuda_runtime.h>
#include <cuda_fp16.h>

// ScaledDotProductAttention: B=4, H=1, S=4096, D=16, fp32.
// out = [context (B*S*D) | attn (B*S*S)]
// scores = QK^T/4 + (w*link + b); masked(true) -> -1e9; softmax; context = attn @ V.
// R9 structure (TQ=8, NT=128, fp16 e buffer, predicated EX2, FFMA2) plus:
// K and V pre-converted to fp16 scratch by a prelude kernel -> rows are 32B,
// quartering the L1 wavefront cost of K/V loads (the measured top cost).

#define BATCH 4
#define SEQ   4096
#define DIM   16
#define TQ    8            // q-rows per CTA
#define NT    128          // threads per CTA
#define NWARP (NT / 32)

#define SMEM_BYTES (TQ * SEQ * 2)   // 65536 B fp16 e buffer

typedef unsigned long long u64;

// fp16 copies of K and V (512 KB total) — device globals, no allocation.
__device__ __align__(16) __half Ksc[BATCH * SEQ * DIM];
__device__ __align__(16) __half Vsc[BATCH * SEQ * DIM];

__device__ __forceinline__ u64 pk2(float lo, float hi) {
    u64 r; asm("mov.b64 %0, {%1, %2};" : "=l"(r) : "f"(lo), "f"(hi)); return r;
}
__device__ __forceinline__ void upk2(u64 v, float& lo, float& hi) {
    asm("mov.b64 {%0, %1}, %2;" : "=f"(lo), "=f"(hi) : "l"(v));
}
__device__ __forceinline__ u64 fma2(u64 a, u64 b, u64 c) {
    u64 d; asm("fma.rn.f32x2 %0, %1, %2, %3;" : "=l"(d) : "l"(a), "l"(b), "l"(c)); return d;
}
__device__ __forceinline__ u64 mul2(u64 a, u64 b) {
    u64 d; asm("mul.rn.f32x2 %0, %1, %2;" : "=l"(d) : "l"(a), "l"(b)); return d;
}
__device__ __forceinline__ u64 h2tof2(unsigned int h) {
    __half2 hh = *(__half2*)&h;
    float2 f = __half22float2(hh);
    return pk2(f.x, f.y);
}

// -------- prelude: fp32 K/V -> fp16 scratch (1 MB read, graph-capturable) --------
__global__ void cvt_kv_kernel(const float4* __restrict__ K4,
                              const float4* __restrict__ V4)
{
    const int i = blockIdx.x * blockDim.x + threadIdx.x;   // 65536 threads, 4 floats each
    float4 k = K4[i];
    float4 v = V4[i];
    __half2 k0 = __floats2half2_rn(k.x, k.y), k1 = __floats2half2_rn(k.z, k.w);
    __half2 v0 = __floats2half2_rn(v.x, v.y), v1 = __floats2half2_rn(v.z, v.w);
    uint2 kp, vp;
    kp.x = *(unsigned int*)&k0; kp.y = *(unsigned int*)&k1;
    vp.x = *(unsigned int*)&v0; vp.y = *(unsigned int*)&v1;
    ((uint2*)Ksc)[i] = kp;
    ((uint2*)Vsc)[i] = vp;
}

__global__ __launch_bounds__(NT, 2)
void sdpa_fused_kernel(const float* __restrict__ Qp,
                       const int*   __restrict__ Mp,
                       const float* __restrict__ Lp,
                       const float* __restrict__ swp,
                       const float* __restrict__ sbp,
                       float* __restrict__ ctx,
                       float* __restrict__ attn)
{
    extern __shared__ __half scr[];                // TQ*SEQ fp16 e values
    __shared__ float qs[TQ * DIM];
    __shared__ float redw[TQ * NWARP];
    __shared__ float sinv[TQ];
    __shared__ float redc[NWARP * 128];            // context partials (2 KB)

    const int tid = threadIdx.x;
    const int wp  = tid >> 5;
    const int ln  = tid & 31;
    const int b   = blockIdx.x / (SEQ / TQ);
    const int q0  = (blockIdx.x % (SEQ / TQ)) * TQ;

    const float LOG2E = 1.44269504088896f;
    const float w2 = (*swp) * LOG2E;
    const float b2 = (*sbp) * LOG2E;
    const float S2 = 0.25f * LOG2E;                // (1/sqrt(16)) * log2e

    qs[tid] = Qp[((size_t)b * SEQ + q0) * DIM + tid];   // NT == TQ*DIM == 128
    __syncthreads();

    u64 q2[TQ * 8];
    #pragma unroll
    for (int q = 0; q < TQ; q++)
        #pragma unroll
        for (int i = 0; i < 8; i++)
            q2[q * 8 + i] = pk2(qs[q * DIM + 2 * i], qs[q * DIM + 2 * i + 1]);

    const uint4*  K16 = (const uint4*)(Ksc + (size_t)b * SEQ * DIM);  // 2 uint4 per row
    const uint4*  V16 = (const uint4*)(Vsc + (size_t)b * SEQ * DIM);
    const float*  Lb  = Lp + (size_t)b * SEQ * SEQ;
    const int*    Mb  = Mp + (size_t)b * SEQ * SEQ;
    float* Ab = attn + (size_t)b * SEQ * SEQ;

    // ============ Phase A: e = ex2(score*log2e) -> fp16 smem; row sums ============
    float sloc[TQ];
    #pragma unroll
    for (int q = 0; q < TQ; q++) sloc[q] = 0.0f;

    #pragma unroll 2
    for (int k = tid; k < SEQ; k += NT) {
        uint4 ka = K16[2 * k];
        uint4 kb = K16[2 * k + 1];
        u64 kk[8];
        kk[0] = h2tof2(ka.x); kk[1] = h2tof2(ka.y);
        kk[2] = h2tof2(ka.z); kk[3] = h2tof2(ka.w);
        kk[4] = h2tof2(kb.x); kk[5] = h2tof2(kb.y);
        kk[6] = h2tof2(kb.z); kk[7] = h2tof2(kb.w);

        float lk[TQ];
        int   mk[TQ];
        #pragma unroll
        for (int q = 0; q < TQ; q++) lk[q] = Lb[(size_t)(q0 + q) * SEQ + k];
        #pragma unroll
        for (int q = 0; q < TQ; q++) mk[q] = Mb[(size_t)(q0 + q) * SEQ + k];

        #pragma unroll
        for (int q = 0; q < TQ; q++) {
            const u64* qq = &q2[q * 8];
            u64 d2 = mul2(qq[0], kk[0]);
            d2 = fma2(qq[1], kk[1], d2);
            d2 = fma2(qq[2], kk[2], d2);
            d2 = fma2(qq[3], kk[3], d2);
            d2 = fma2(qq[4], kk[4], d2);
            d2 = fma2(qq[5], kk[5], d2);
            d2 = fma2(qq[6], kk[6], d2);
            d2 = fma2(qq[7], kk[7], d2);
            float dl, dh;
            upk2(d2, dl, dh);
            float dot = dl + dh;
            float sc2 = fmaf(w2, lk[q], b2);
            sc2 = fmaf(dot, S2, sc2);
            float e = 0.0f;
            if (!mk[q])
                asm("ex2.approx.ftz.f32 %0, %1;" : "=f"(e) : "f"(sc2));
            __half he = __float2half_rn(e);
            scr[q * SEQ + k] = he;
            sloc[q] += __half2float(he);       // sum the ROUNDED value
        }
    }

    // ---- reduce row sums ----
    #pragma unroll
    for (int q = 0; q < TQ; q++) {
        #pragma unroll
        for (int o = 16; o > 0; o >>= 1)
            sloc[q] += __shfl_xor_sync(0xffffffffu, sloc[q], o);
    }
    if (ln == 0) {
        #pragma unroll
        for (int q = 0; q < TQ; q++) redw[q * NWARP + wp] = sloc[q];
    }
    __syncthreads();
    if (tid < TQ) {
        float s = 0.0f;
        #pragma unroll
        for (int t = 0; t < NWARP; t++) s += redw[tid * NWARP + t];
        sinv[tid] = 1.0f / s;
    }
    __syncthreads();

    // ============ Phase E: attn = e * inv; context accumulate (packed) ============
    float inv[TQ];
    #pragma unroll
    for (int q = 0; q < TQ; q++) inv[q] = sinv[q];

    u64 acc2[TQ * 8];
    #pragma unroll
    for (int i = 0; i < TQ * 8; i++) acc2[i] = 0ull;

    #pragma unroll 2
    for (int k = tid; k < SEQ; k += NT) {
        uint4 va = V16[2 * k];
        uint4 vb = V16[2 * k + 1];
        u64 vv[8];
        vv[0] = h2tof2(va.x); vv[1] = h2tof2(va.y);
        vv[2] = h2tof2(va.z); vv[3] = h2tof2(va.w);
        vv[4] = h2tof2(vb.x); vv[5] = h2tof2(vb.y);
        vv[6] = h2tof2(vb.z); vv[7] = h2tof2(vb.w);

        #pragma unroll
        for (int q = 0; q < TQ; q++) {
            float a = __half2float(scr[q * SEQ + k]) * inv[q];
            Ab[(size_t)(q0 + q) * SEQ + k] = a;
            u64 aa = pk2(a, a);
            u64* A = &acc2[q * 8];
            A[0] = fma2(aa, vv[0], A[0]);
            A[1] = fma2(aa, vv[1], A[1]);
            A[2] = fma2(aa, vv[2], A[2]);
            A[3] = fma2(aa, vv[3], A[3]);
            A[4] = fma2(aa, vv[4], A[4]);
            A[5] = fma2(aa, vv[5], A[5]);
            A[6] = fma2(aa, vv[6], A[6]);
            A[7] = fma2(aa, vv[7], A[7]);
        }
    }

    // ---- unpack + multi-value warp butterfly: lane ln owns {4ln..4ln+3} ----
    float acc[TQ * DIM];
    #pragma unroll
    for (int i = 0; i < TQ * 8; i++)
        upk2(acc2[i], acc[2 * i], acc[2 * i + 1]);

    #pragma unroll
    for (int o = 16, n = 64; o >= 1; o >>= 1, n >>= 1) {
        const bool hi = (ln & o) != 0;
        #pragma unroll
        for (int i = 0; i < n; i++) {
            float s    = hi ? acc[i] : acc[i + n];
            float r    = __shfl_xor_sync(0xffffffffu, s, o);
            float mine = hi ? acc[i + n] : acc[i];
            acc[i] = mine + r;
        }
    }
    *(float4*)&redc[wp * 128 + 4 * ln] = make_float4(acc[0], acc[1], acc[2], acc[3]);
    __syncthreads();

    {   // NT == 128: every thread finalizes one (q, d) output
        float s = 0.0f;
        #pragma unroll
        for (int ww = 0; ww < NWARP; ww++)
            s += redc[ww * 128 + tid];
        const int q = tid >> 4, d = tid & 15;
        ctx[((size_t)b * SEQ + q0 + q) * DIM + d] = s;
    }
}

extern "C" void kernel_launch(void* const* d_in, const int* in_sizes, int n_in,
                              void* d_out, int out_size)
{
    const float* Q  = (const float*)d_in[0];
    const float* K  = (const float*)d_in[1];
    const float* V  = (const float*)d_in[2];
    const int*   M  = (const int*)d_in[3];
    const float* L  = (const float*)d_in[4];
    const float* sw = (const float*)d_in[5];
    const float* sb = (const float*)d_in[6];

    float* ctx  = (float*)d_out;                               // B*S*D
    float* attn = (float*)d_out + (size_t)BATCH * SEQ * DIM;   // B*S*S

    // prelude: K/V -> fp16 scratch (262144 elems / 4 per thread)
    cvt_kv_kernel<<<256, 256>>>((const float4*)K, (const float4*)V);

    cudaFuncSetAttribute(sdpa_fused_kernel,
                         cudaFuncAttributeMaxDynamicSharedMemorySize, SMEM_BYTES);

    dim3 grid(BATCH * (SEQ / TQ));
    sdpa_fused_kernel<<<grid, NT, SMEM_BYTES>>>(Q, M, L, sw, sb, ctx, attn);
}

// round 13
// speedup vs baseline: 2.2835x; 1.2075x over previous
#include <cuda_runtime.h>
#include <cuda_fp16.h>

// ScaledDotProductAttention: B=4, H=1, S=4096, D=16, fp32.
// out = [context (B*S*D) | attn (B*S*S)]
// scores = QK^T/4 + (w*link + b); masked(true) -> -1e9; softmax; context = attn @ V.
// fp16 K/V scratch (quarters K/V L1 wavefronts, proven R12) combined with
// TQ=4 / 3 CTAs/SM = 12 warps (occupancy, proven R10) — R10's L1 saturation
// is exactly the cost R12 removed.

#define BATCH 4
#define SEQ   4096
#define DIM   16
#define TQ    4            // q-rows per CTA
#define NT    128          // threads per CTA
#define NWARP (NT / 32)

#define SMEM_BYTES (TQ * SEQ * 2)   // 32768 B fp16 e buffer

typedef unsigned long long u64;

// fp16 copies of K and V (512 KB total) — device globals, no allocation.
__device__ __align__(16) __half Ksc[BATCH * SEQ * DIM];
__device__ __align__(16) __half Vsc[BATCH * SEQ * DIM];

__device__ __forceinline__ u64 pk2(float lo, float hi) {
    u64 r; asm("mov.b64 %0, {%1, %2};" : "=l"(r) : "f"(lo), "f"(hi)); return r;
}
__device__ __forceinline__ void upk2(u64 v, float& lo, float& hi) {
    asm("mov.b64 {%0, %1}, %2;" : "=f"(lo), "=f"(hi) : "l"(v));
}
__device__ __forceinline__ u64 fma2(u64 a, u64 b, u64 c) {
    u64 d; asm("fma.rn.f32x2 %0, %1, %2, %3;" : "=l"(d) : "l"(a), "l"(b), "l"(c)); return d;
}
__device__ __forceinline__ u64 mul2(u64 a, u64 b) {
    u64 d; asm("mul.rn.f32x2 %0, %1, %2;" : "=l"(d) : "l"(a), "l"(b)); return d;
}
__device__ __forceinline__ u64 h2tof2(unsigned int h) {
    __half2 hh = *(__half2*)&h;
    float2 f = __half22float2(hh);
    return pk2(f.x, f.y);
}

// -------- prelude: fp32 K/V -> fp16 scratch (1 MB read, graph-capturable) --------
__global__ void cvt_kv_kernel(const float4* __restrict__ K4,
                              const float4* __restrict__ V4)
{
    const int i = blockIdx.x * blockDim.x + threadIdx.x;   // 65536 threads, 4 floats each
    float4 k = K4[i];
    float4 v = V4[i];
    __half2 k0 = __floats2half2_rn(k.x, k.y), k1 = __floats2half2_rn(k.z, k.w);
    __half2 v0 = __floats2half2_rn(v.x, v.y), v1 = __floats2half2_rn(v.z, v.w);
    uint2 kp, vp;
    kp.x = *(unsigned int*)&k0; kp.y = *(unsigned int*)&k1;
    vp.x = *(unsigned int*)&v0; vp.y = *(unsigned int*)&v1;
    ((uint2*)Ksc)[i] = kp;
    ((uint2*)Vsc)[i] = vp;
}

__global__ __launch_bounds__(NT, 3)
void sdpa_fused_kernel(const float* __restrict__ Qp,
                       const int*   __restrict__ Mp,
                       const float* __restrict__ Lp,
                       const float* __restrict__ swp,
                       const float* __restrict__ sbp,
                       float* __restrict__ ctx,
                       float* __restrict__ attn)
{
    extern __shared__ __half scr[];                // TQ*SEQ fp16 e values
    __shared__ float qs[TQ * DIM];
    __shared__ float redw[TQ * NWARP];
    __shared__ float sinv[TQ];
    __shared__ float redc[NWARP * TQ * DIM];       // context partials (1 KB)

    const int tid = threadIdx.x;
    const int wp  = tid >> 5;
    const int ln  = tid & 31;
    const int b   = blockIdx.x / (SEQ / TQ);
    const int q0  = (blockIdx.x % (SEQ / TQ)) * TQ;

    const float LOG2E = 1.44269504088896f;
    const float w2 = (*swp) * LOG2E;
    const float b2 = (*sbp) * LOG2E;
    const float S2 = 0.25f * LOG2E;                // (1/sqrt(16)) * log2e

    if (tid < TQ * DIM)
        qs[tid] = Qp[((size_t)b * SEQ + q0) * DIM + tid];
    __syncthreads();

    u64 q2[TQ * 8];
    #pragma unroll
    for (int q = 0; q < TQ; q++)
        #pragma unroll
        for (int i = 0; i < 8; i++)
            q2[q * 8 + i] = pk2(qs[q * DIM + 2 * i], qs[q * DIM + 2 * i + 1]);

    const uint4*  K16 = (const uint4*)(Ksc + (size_t)b * SEQ * DIM);  // 2 uint4 per row
    const uint4*  V16 = (const uint4*)(Vsc + (size_t)b * SEQ * DIM);
    const float*  Lb  = Lp + (size_t)b * SEQ * SEQ;
    const int*    Mb  = Mp + (size_t)b * SEQ * SEQ;
    float* Ab = attn + (size_t)b * SEQ * SEQ;

    // ============ Phase A: e = ex2(score*log2e) -> fp16 smem; row sums ============
    float sloc[TQ];
    #pragma unroll
    for (int q = 0; q < TQ; q++) sloc[q] = 0.0f;

    #pragma unroll 2
    for (int k = tid; k < SEQ; k += NT) {
        uint4 ka = K16[2 * k];
        uint4 kb = K16[2 * k + 1];
        u64 kk[8];
        kk[0] = h2tof2(ka.x); kk[1] = h2tof2(ka.y);
        kk[2] = h2tof2(ka.z); kk[3] = h2tof2(ka.w);
        kk[4] = h2tof2(kb.x); kk[5] = h2tof2(kb.y);
        kk[6] = h2tof2(kb.z); kk[7] = h2tof2(kb.w);

        float lk[TQ];
        int   mk[TQ];
        #pragma unroll
        for (int q = 0; q < TQ; q++) lk[q] = Lb[(size_t)(q0 + q) * SEQ + k];
        #pragma unroll
        for (int q = 0; q < TQ; q++) mk[q] = Mb[(size_t)(q0 + q) * SEQ + k];

        #pragma unroll
        for (int q = 0; q < TQ; q++) {
            const u64* qq = &q2[q * 8];
            u64 d2 = mul2(qq[0], kk[0]);
            d2 = fma2(qq[1], kk[1], d2);
            d2 = fma2(qq[2], kk[2], d2);
            d2 = fma2(qq[3], kk[3], d2);
            d2 = fma2(qq[4], kk[4], d2);
            d2 = fma2(qq[5], kk[5], d2);
            d2 = fma2(qq[6], kk[6], d2);
            d2 = fma2(qq[7], kk[7], d2);
            float dl, dh;
            upk2(d2, dl, dh);
            float dot = dl + dh;
            float sc2 = fmaf(w2, lk[q], b2);
            sc2 = fmaf(dot, S2, sc2);
            float e = 0.0f;
            if (!mk[q])
                asm("ex2.approx.ftz.f32 %0, %1;" : "=f"(e) : "f"(sc2));
            __half he = __float2half_rn(e);
            scr[q * SEQ + k] = he;
            sloc[q] += __half2float(he);       // sum the ROUNDED value
        }
    }

    // ---- reduce row sums ----
    #pragma unroll
    for (int q = 0; q < TQ; q++) {
        #pragma unroll
        for (int o = 16; o > 0; o >>= 1)
            sloc[q] += __shfl_xor_sync(0xffffffffu, sloc[q], o);
    }
    if (ln == 0) {
        #pragma unroll
        for (int q = 0; q < TQ; q++) redw[q * NWARP + wp] = sloc[q];
    }
    __syncthreads();
    if (tid < TQ) {
        float s = 0.0f;
        #pragma unroll
        for (int t = 0; t < NWARP; t++) s += redw[tid * NWARP + t];
        sinv[tid] = 1.0f / s;
    }
    __syncthreads();

    // ============ Phase E: attn = e * inv; context accumulate (packed) ============
    float inv[TQ];
    #pragma unroll
    for (int q = 0; q < TQ; q++) inv[q] = sinv[q];

    u64 acc2[TQ * 8];
    #pragma unroll
    for (int i = 0; i < TQ * 8; i++) acc2[i] = 0ull;

    #pragma unroll 2
    for (int k = tid; k < SEQ; k += NT) {
        uint4 va = V16[2 * k];
        uint4 vb = V16[2 * k + 1];
        u64 vv[8];
        vv[0] = h2tof2(va.x); vv[1] = h2tof2(va.y);
        vv[2] = h2tof2(va.z); vv[3] = h2tof2(va.w);
        vv[4] = h2tof2(vb.x); vv[5] = h2tof2(vb.y);
        vv[6] = h2tof2(vb.z); vv[7] = h2tof2(vb.w);

        #pragma unroll
        for (int q = 0; q < TQ; q++) {
            float a = __half2float(scr[q * SEQ + k]) * inv[q];
            Ab[(size_t)(q0 + q) * SEQ + k] = a;
            u64 aa = pk2(a, a);
            u64* A = &acc2[q * 8];
            A[0] = fma2(aa, vv[0], A[0]);
            A[1] = fma2(aa, vv[1], A[1]);
            A[2] = fma2(aa, vv[2], A[2]);
            A[3] = fma2(aa, vv[3], A[3]);
            A[4] = fma2(aa, vv[4], A[4]);
            A[5] = fma2(aa, vv[5], A[5]);
            A[6] = fma2(aa, vv[6], A[6]);
            A[7] = fma2(aa, vv[7], A[7]);
        }
    }

    // ---- unpack + multi-value warp butterfly: 64 sums -> lane ln owns {2ln, 2ln+1} ----
    float acc[TQ * DIM];
    #pragma unroll
    for (int i = 0; i < TQ * 8; i++)
        upk2(acc2[i], acc[2 * i], acc[2 * i + 1]);

    #pragma unroll
    for (int o = 16, n = 32; o >= 1; o >>= 1, n >>= 1) {
        const bool hi = (ln & o) != 0;
        #pragma unroll
        for (int i = 0; i < n; i++) {
            float s    = hi ? acc[i] : acc[i + n];
            float r    = __shfl_xor_sync(0xffffffffu, s, o);
            float mine = hi ? acc[i + n] : acc[i];
            acc[i] = mine + r;
        }
    }
    *(float2*)&redc[wp * (TQ * DIM) + 2 * ln] = make_float2(acc[0], acc[1]);
    __syncthreads();

    if (tid < TQ * DIM) {
        float s = 0.0f;
        #pragma unroll
        for (int ww = 0; ww < NWARP; ww++)
            s += redc[ww * (TQ * DIM) + tid];
        const int q = tid >> 4, d = tid & 15;
        ctx[((size_t)b * SEQ + q0 + q) * DIM + d] = s;
    }
}

extern "C" void kernel_launch(void* const* d_in, const int* in_sizes, int n_in,
                              void* d_out, int out_size)
{
    const float* Q  = (const float*)d_in[0];
    const float* K  = (const float*)d_in[1];
    const float* V  = (const float*)d_in[2];
    const int*   M  = (const int*)d_in[3];
    const float* L  = (const float*)d_in[4];
    const float* sw = (const float*)d_in[5];
    const float* sb = (const float*)d_in[6];

    float* ctx  = (float*)d_out;                               // B*S*D
    float* attn = (float*)d_out + (size_t)BATCH * SEQ * DIM;   // B*S*S

    // prelude: K/V -> fp16 scratch (262144 elems / 4 per thread)
    cvt_kv_kernel<<<256, 256>>>((const float4*)K, (const float4*)V);

    cudaFuncSetAttribute(sdpa_fused_kernel,
                         cudaFuncAttributeMaxDynamicSharedMemorySize, SMEM_BYTES);

    dim3 grid(BATCH * (SEQ / TQ));
    sdpa_fused_kernel<<<grid, NT, SMEM_BYTES>>>(Q, M, L, sw, sb, ctx, attn);
}